// round 15
// baseline (speedup 1.0000x reference)
#include <cuda_runtime.h>
#include <cuda_fp16.h>
#include <math.h>

#define NN    50000
#define EE    500000
#define ET    550000          // EE + NN self-loops
#define FIN   128
#define HD1   256             // HEADS*HID
#define HEADS 8
#define HID   32
#define OUTC  64
#define NBLK  196             // ceil(NN/256)
#define STA   8               // As row stride in words (16 halves, no pad; swizzled)

// ---------------- scratch (static device arrays; no cudaMalloc) -------------
__device__ __half g_h1h[NN * HD1];   // gemm1 output (fp16)
__device__ __half g_h1b[NN * HD1];   // layer-1 GAT output, post bias+ELU (fp16)
__device__ float  g_al1[NN * HEADS];
__device__ float  g_ar1[NN * HEADS];
__device__ __half g_h2h[NN * OUTC];  // gemm2 output (fp16)
__device__ float  g_al2[NN];
__device__ float  g_ar2[NN];

__device__ int g_deg  [NN];
__device__ int g_cur  [NN];
__device__ int g_start[NN];
__device__ int g_scan [NN];
__device__ int g_bsum [256];
__device__ int g_esrc [ET];

// ---------------- streams/events (host objects, created at static init) -----
struct HxStreams {
    cudaStream_t s1;
    cudaEvent_t fork, join;
    HxStreams() {
        cudaStreamCreateWithFlags(&s1, cudaStreamNonBlocking);
        cudaEventCreateWithFlags(&fork, cudaEventDisableTiming);
        cudaEventCreateWithFlags(&join, cudaEventDisableTiming);
    }
};
static HxStreams g_hx;

// ---------------- helpers ---------------------------------------------------
__device__ __forceinline__ float lrelu(float v) { return v > 0.f ? v : 0.2f * v; }

__device__ __forceinline__ int edge_dst(const int* __restrict__ ei, int e) {
    return (e < EE) ? ei[EE + e] : (e - EE);
}
__device__ __forceinline__ int edge_src(const int* __restrict__ ei, int e) {
    return (e < EE) ? ei[e] : (e - EE);
}

__device__ __forceinline__ unsigned packh2(float a, float b) {
    __half2 h = __floats2half2_rn(a, b);
    return *(unsigned*)&h;
}

__device__ __forceinline__ void mma_fp16(float c[4], const unsigned a[4], const unsigned b[2]) {
    asm volatile(
        "mma.sync.aligned.m16n8k16.row.col.f32.f16.f16.f32 "
        "{%0,%1,%2,%3}, {%4,%5,%6,%7}, {%8,%9}, {%0,%1,%2,%3};"
        : "+f"(c[0]), "+f"(c[1]), "+f"(c[2]), "+f"(c[3])
        : "r"(a[0]), "r"(a[1]), "r"(a[2]), "r"(a[3]), "r"(b[0]), "r"(b[1]));
}

// A-pair loader: produces pairs (k, k+1) and (k+8, k+9) as packed half2 words
__device__ __forceinline__ void load_a_pair(const float* p, unsigned& u0, unsigned& u1) {
    float2 f0 = *(const float2*)p;
    float2 f1 = *(const float2*)(p + 8);
    u0 = packh2(f0.x, f0.y);
    u1 = packh2(f1.x, f1.y);
}
__device__ __forceinline__ void load_a_pair(const __half* p, unsigned& u0, unsigned& u1) {
    u0 = *(const unsigned*)p;
    u1 = *(const unsigned*)(p + 8);
}

// ---------------- CSR build --------------------------------------------------
__global__ void k_zero() {
    int i = blockIdx.x * blockDim.x + threadIdx.x;
    if (i < NN) { g_deg[i] = 0; g_cur[i] = 0; }
}

__global__ void k_hist(const int* __restrict__ ei) {
    int e = blockIdx.x * blockDim.x + threadIdx.x;
    if (e >= ET) return;
    atomicAdd(&g_deg[edge_dst(ei, e)], 1);
}

__global__ void k_scanA() {
    __shared__ int s[256];
    int i = blockIdx.x * 256 + threadIdx.x;
    int v = (i < NN) ? g_deg[i] : 0;
    s[threadIdx.x] = v;
    __syncthreads();
    #pragma unroll
    for (int off = 1; off < 256; off <<= 1) {
        int t = (threadIdx.x >= off) ? s[threadIdx.x - off] : 0;
        __syncthreads();
        s[threadIdx.x] += t;
        __syncthreads();
    }
    if (i < NN) g_scan[i] = s[threadIdx.x];
    if (threadIdx.x == 255) g_bsum[blockIdx.x] = s[255];
}

__global__ void k_scanC() {
    __shared__ int red[256];
    int tid = threadIdx.x;
    red[tid] = (tid < (int)blockIdx.x) ? g_bsum[tid] : 0;
    __syncthreads();
    #pragma unroll
    for (int off = 128; off > 0; off >>= 1) {
        if (tid < off) red[tid] += red[tid + off];
        __syncthreads();
    }
    int base = red[0];
    int i = blockIdx.x * 256 + tid;
    if (i < NN) g_start[i] = g_scan[i] - g_deg[i] + base;
}

__global__ void k_scatter(const int* __restrict__ ei) {
    int e = blockIdx.x * blockDim.x + threadIdx.x;
    if (e >= ET) return;
    int d = edge_dst(ei, e);
    int pos = g_start[d] + atomicAdd(&g_cur[d], 1);
    g_esrc[pos] = edge_src(ei, e);
}

// ---------------- FP16 tensor-core GEMM, B resident in smem ------------------
template<int BN, int KK, typename AT>
__global__ __launch_bounds__(256, 2) void k_gemm_fp16(
    const AT* __restrict__ A, const float* __restrict__ B,
    __half* __restrict__ Ch, int nrows, int ncols)
{
    constexpr int WN  = BN / 32;
    constexpr int WM  = 8 / WN;
    constexpr int MT  = 128 / (WM * 16);
    constexpr int NT  = 4;
    constexpr int STB = KK / 2 + 8;     // B col stride (words); /2 ≡ 4 mod 16
    constexpr int NC  = KK / 16;

    extern __shared__ unsigned sm[];
    unsigned* Bs = sm;                  // [BN][STB]
    unsigned* As = sm + BN * STB;       // [128][STA]

    int tid = threadIdx.x;
    int lane = tid & 31, warp = tid >> 5;
    int g = lane >> 2, tig = lane & 3;
    int wm = warp % WM, wn = warp / WM;
    int rowBase = blockIdx.x * 128, colBase = blockIdx.y * BN;

    // ---- fill B slab once ----
    {
        int tig_f = tid >> 6;           // 0..3 : pair-slot
        int cc    = tid & 63;
        #pragma unroll
        for (int c16 = 0; c16 < NC; ++c16) {
            #pragma unroll
            for (int hb = 0; hb < BN / 64; ++hb) {
                int col = cc + hb * 64;
                const float* bp = B + (size_t)(c16 * 16 + 2 * tig_f) * ncols + colBase + col;
                float v0 = bp[0];
                float v1 = bp[(size_t)ncols];
                float v8 = bp[(size_t)8 * ncols];
                float v9 = bp[(size_t)9 * ncols];
                int slot = tig_f ^ (col & 3);
                *(uint2*)&Bs[col * STB + c16 * 8 + 2 * slot] =
                    make_uint2(packh2(v0, v1), packh2(v8, v9));
            }
        }
    }

    float c[MT][NT][4] = {};

    int tig_a = tid & 3, rr = tid >> 2;   // A fill: rows rr, rr+64; pair-slot tig_a
    unsigned au[2][2];

    // prefetch chunk 0
    #pragma unroll
    for (int r = 0; r < 2; ++r) {
        int grow = rowBase + rr + r * 64;
        if (grow < nrows)
            load_a_pair(A + (size_t)grow * KK + 2 * tig_a, au[r][0], au[r][1]);
        else { au[r][0] = 0u; au[r][1] = 0u; }
    }

    for (int kci = 0; kci < NC; ++kci) {
        #pragma unroll
        for (int r = 0; r < 2; ++r) {
            int row = rr + r * 64;
            *(uint2*)&As[row * STA + 2 * (tig_a ^ (row & 3))] =
                make_uint2(au[r][0], au[r][1]);
        }
        __syncthreads();

        if (kci + 1 < NC) {
            int kc = (kci + 1) * 16;
            #pragma unroll
            for (int r = 0; r < 2; ++r) {
                int grow = rowBase + rr + r * 64;
                if (grow < nrows)
                    load_a_pair(A + (size_t)grow * KK + kc + 2 * tig_a, au[r][0], au[r][1]);
                else { au[r][0] = 0u; au[r][1] = 0u; }
            }
        }

        unsigned a[MT][4], b[NT][2];
        int sw = 2 * (tig ^ (g & 3));
        #pragma unroll
        for (int mt = 0; mt < MT; ++mt) {
            int rlo = wm * (MT * 16) + mt * 16 + g;
            uint2 lo = *(const uint2*)&As[rlo * STA + sw];
            uint2 hi = *(const uint2*)&As[(rlo + 8) * STA + sw];
            a[mt][0] = lo.x; a[mt][2] = lo.y;
            a[mt][1] = hi.x; a[mt][3] = hi.y;
        }
        #pragma unroll
        for (int nt = 0; nt < NT; ++nt) {
            int cn = wn * 32 + nt * 8 + g;
            uint2 bb = *(const uint2*)&Bs[cn * STB + kci * 8 + sw];
            b[nt][0] = bb.x; b[nt][1] = bb.y;
        }
        #pragma unroll
        for (int mt = 0; mt < MT; ++mt)
            #pragma unroll
            for (int nt = 0; nt < NT; ++nt)
                mma_fp16(c[mt][nt], a[mt], b[nt]);
        __syncthreads();
    }

    // epilogue (fp16 out)
    #pragma unroll
    for (int mt = 0; mt < MT; ++mt) {
        #pragma unroll
        for (int nt = 0; nt < NT; ++nt) {
            int row0 = rowBase + wm * (MT * 16) + mt * 16 + g;
            int row1 = row0 + 8;
            int col  = colBase + wn * 32 + nt * 8 + tig * 2;
            if (row0 < nrows)
                *(__half2*)(Ch + (size_t)row0 * ncols + col) =
                    __floats2half2_rn(c[mt][nt][0], c[mt][nt][1]);
            if (row1 < nrows)
                *(__half2*)(Ch + (size_t)row1 * ncols + col) =
                    __floats2half2_rn(c[mt][nt][2], c[mt][nt][3]);
        }
    }
}

// ---------------- layer-1 attention logits (warp per node, fp16 h1) ---------
__global__ __launch_bounds__(256) void k_logits1(
    const float* __restrict__ a_src, const float* __restrict__ a_dst)
{
    int warp = threadIdx.x >> 5, lane = threadIdx.x & 31;
    int n = blockIdx.x * 8 + warp;
    if (n >= NN) return;
    int h = lane >> 2;
    int c0 = lane * 8;
    uint4 q = *(const uint4*)(g_h1h + (size_t)n * HD1 + c0);
    const __half2* hh = (const __half2*)&q;
    float v[8];
    #pragma unroll
    for (int p = 0; p < 4; ++p) {
        float2 f = __half22float2(hh[p]);
        v[2 * p] = f.x; v[2 * p + 1] = f.y;
    }
    float sa = 0.f, sd = 0.f;
    #pragma unroll
    for (int i = 0; i < 8; ++i) {
        int cc = (c0 + i) & 31;
        sa += v[i] * a_src[h * HID + cc];
        sd += v[i] * a_dst[h * HID + cc];
    }
    sa += __shfl_xor_sync(0xffffffffu, sa, 1);
    sa += __shfl_xor_sync(0xffffffffu, sa, 2);
    sd += __shfl_xor_sync(0xffffffffu, sd, 1);
    sd += __shfl_xor_sync(0xffffffffu, sd, 2);
    if ((lane & 3) == 0) { g_al1[n * HEADS + h] = sa; g_ar1[n * HEADS + h] = sd; }
}

// ---------------- fused layer-1 GAT: split-channel (2 warps/node), ----------
// predicated 4-wide edge loop. gridDim.y = 2; warp covers 128 channels,
// each lane 4 channels (8B gather per edge).
__global__ __launch_bounds__(256) void k_gat1(const float* __restrict__ b1) {
    int warp = threadIdx.x >> 5, lane = threadIdx.x & 31;
    int n = blockIdx.x * 8 + warp;
    if (n >= NN) return;
    int cb = blockIdx.y * 128;             // channel base (0 or 128)
    int h  = (cb >> 5) + (lane >> 3);      // head for this lane's channels
    int beg = g_start[n], deg = g_deg[n];
    float ard = g_ar1[n * HEADS + h];

    const __half* hbase = g_h1h + cb + lane * 4;
    float sum = 0.f;
    float acc[4] = {};
    int iters = (deg + 3) >> 2;
    for (int it = 0; it < iters; ++it) {
        int i = it * 4;
        int i1 = min(i + 1, deg - 1);
        int i2 = min(i + 2, deg - 1);
        int i3 = min(i + 3, deg - 1);
        int s0 = g_esrc[beg + i];
        int s1 = g_esrc[beg + i1];
        int s2 = g_esrc[beg + i2];
        int s3 = g_esrc[beg + i3];
        float p0 = __expf(lrelu(g_al1[s0 * HEADS + h] + ard));
        float p1 = (i + 1 < deg) ? __expf(lrelu(g_al1[s1 * HEADS + h] + ard)) : 0.f;
        float p2 = (i + 2 < deg) ? __expf(lrelu(g_al1[s2 * HEADS + h] + ard)) : 0.f;
        float p3 = (i + 3 < deg) ? __expf(lrelu(g_al1[s3 * HEADS + h] + ard)) : 0.f;
        sum += (p0 + p1) + (p2 + p3);
        uint2 q0 = *(const uint2*)(hbase + (size_t)s0 * HD1);
        uint2 q1 = *(const uint2*)(hbase + (size_t)s1 * HD1);
        uint2 q2 = *(const uint2*)(hbase + (size_t)s2 * HD1);
        uint2 q3 = *(const uint2*)(hbase + (size_t)s3 * HD1);
        const __half2* f0 = (const __half2*)&q0;
        const __half2* f1 = (const __half2*)&q1;
        const __half2* f2 = (const __half2*)&q2;
        const __half2* f3 = (const __half2*)&q3;
        #pragma unroll
        for (int p = 0; p < 2; ++p) {
            float2 a0 = __half22float2(f0[p]);
            float2 a1 = __half22float2(f1[p]);
            float2 a2 = __half22float2(f2[p]);
            float2 a3 = __half22float2(f3[p]);
            acc[2 * p]     += (p0 * a0.x + p1 * a1.x) + (p2 * a2.x + p3 * a3.x);
            acc[2 * p + 1] += (p0 * a0.y + p1 * a1.y) + (p2 * a2.y + p3 * a3.y);
        }
    }
    float r = 1.f / (sum + 1e-16f);
    int c = cb + lane * 4;
    __half2 w[2];
    #pragma unroll
    for (int j = 0; j < 2; ++j) {
        float t0 = acc[2 * j] * r + b1[c + 2 * j];
        float t1 = acc[2 * j + 1] * r + b1[c + 2 * j + 1];
        t0 = t0 > 0.f ? t0 : expm1f(t0);
        t1 = t1 > 0.f ? t1 : expm1f(t1);
        w[j] = __floats2half2_rn(t0, t1);
    }
    *(uint2*)(g_h1b + (size_t)n * HD1 + c) = *(const uint2*)w;
}

// ---------------- layer-2 attention logits (fp16 h2) -------------------------
__global__ __launch_bounds__(256) void k_logits2(
    const float* __restrict__ a_src, const float* __restrict__ a_dst)
{
    int warp = threadIdx.x >> 5, lane = threadIdx.x & 31;
    int n = blockIdx.x * 8 + warp;
    if (n >= NN) return;
    float2 v = __half22float2(((const __half2*)(g_h2h + (size_t)n * OUTC))[lane]);
    int c = lane * 2;
    float sa = v.x * a_src[c] + v.y * a_src[c + 1];
    float sd = v.x * a_dst[c] + v.y * a_dst[c + 1];
    #pragma unroll
    for (int off = 16; off > 0; off >>= 1) {
        sa += __shfl_xor_sync(0xffffffffu, sa, off);
        sd += __shfl_xor_sync(0xffffffffu, sd, off);
    }
    if (lane == 0) { g_al2[n] = sa; g_ar2[n] = sd; }
}

// ---------------- fused layer-2 GAT + bias + log-softmax ---------------------
// predicated 4-wide edge loop.
__global__ __launch_bounds__(256) void k_gat2(
    const float* __restrict__ b2, float* __restrict__ out)
{
    int warp = threadIdx.x >> 5, lane = threadIdx.x & 31;
    int n = blockIdx.x * 8 + warp;
    if (n >= NN) return;
    int beg = g_start[n], deg = g_deg[n];
    float ard = g_ar2[n];

    const __half* hbase = g_h2h + lane * 2;
    float sum = 0.f;
    float2 acc = make_float2(0.f, 0.f);
    int iters = (deg + 3) >> 2;
    for (int it = 0; it < iters; ++it) {
        int i = it * 4;
        int i1 = min(i + 1, deg - 1);
        int i2 = min(i + 2, deg - 1);
        int i3 = min(i + 3, deg - 1);
        int s0 = g_esrc[beg + i];
        int s1 = g_esrc[beg + i1];
        int s2 = g_esrc[beg + i2];
        int s3 = g_esrc[beg + i3];
        float p0 = __expf(lrelu(g_al2[s0] + ard));
        float p1 = (i + 1 < deg) ? __expf(lrelu(g_al2[s1] + ard)) : 0.f;
        float p2 = (i + 2 < deg) ? __expf(lrelu(g_al2[s2] + ard)) : 0.f;
        float p3 = (i + 3 < deg) ? __expf(lrelu(g_al2[s3] + ard)) : 0.f;
        sum += (p0 + p1) + (p2 + p3);
        float2 x0 = __half22float2(*(const __half2*)(hbase + (size_t)s0 * OUTC));
        float2 x1 = __half22float2(*(const __half2*)(hbase + (size_t)s1 * OUTC));
        float2 x2 = __half22float2(*(const __half2*)(hbase + (size_t)s2 * OUTC));
        float2 x3 = __half22float2(*(const __half2*)(hbase + (size_t)s3 * OUTC));
        acc.x += (p0 * x0.x + p1 * x1.x) + (p2 * x2.x + p3 * x3.x);
        acc.y += (p0 * x0.y + p1 * x1.y) + (p2 * x2.y + p3 * x3.y);
    }
    float r = 1.f / (sum + 1e-16f);
    int c = lane * 2;
    float v0 = acc.x * r + b2[c];
    float v1 = acc.y * r + b2[c + 1];

    float m = fmaxf(v0, v1);
    #pragma unroll
    for (int off = 16; off > 0; off >>= 1)
        m = fmaxf(m, __shfl_xor_sync(0xffffffffu, m, off));
    float ss = expf(v0 - m) + expf(v1 - m);
    #pragma unroll
    for (int off = 16; off > 0; off >>= 1)
        ss += __shfl_xor_sync(0xffffffffu, ss, off);
    float l = m + logf(ss);
    out[(size_t)n * OUTC + c]     = v0 - l;
    out[(size_t)n * OUTC + c + 1] = v1 - l;
}

// ---------------- launcher ---------------------------------------------------
extern "C" void kernel_launch(void* const* d_in, const int* in_sizes, int n_in,
                              void* d_out, int out_size)
{
    const float* x   = (const float*)d_in[0];
    const int*   ei  = (const int*)d_in[1];
    const float* W1  = (const float*)d_in[2];
    const float* a1s = (const float*)d_in[3];
    const float* a1d = (const float*)d_in[4];
    const float* b1  = (const float*)d_in[5];
    const float* W2  = (const float*)d_in[6];
    const float* a2s = (const float*)d_in[7];
    const float* a2d = (const float*)d_in[8];
    const float* b2  = (const float*)d_in[9];
    float* out = (float*)d_out;

    __half *h1hp, *h1bp, *h2hp;
    cudaGetSymbolAddress((void**)&h1hp, g_h1h);
    cudaGetSymbolAddress((void**)&h1bp, g_h1b);
    cudaGetSymbolAddress((void**)&h2hp, g_h2h);

    const int EB  = (ET + 255) / 256;
    const int NB  = (NN + 255) / 256;
    const int NWB = (NN + 7) / 8;

    const int SM1 = (128 * (128 / 2 + 8) + 128 * STA) * 4;   // 40960 B
    const int SM2 = (64 * (256 / 2 + 8) + 128 * STA) * 4;    // 38912 B
    cudaFuncSetAttribute(k_gemm_fp16<128, 128, float>,
                         cudaFuncAttributeMaxDynamicSharedMemorySize, SM1);
    cudaFuncSetAttribute(k_gemm_fp16<64, 256, __half>,
                         cudaFuncAttributeMaxDynamicSharedMemorySize, SM2);

    cudaStream_t s1 = g_hx.s1;

    // fork: CSR build on s1, concurrent with gemm1+logits1 on main stream
    cudaEventRecord(g_hx.fork, 0);
    cudaStreamWaitEvent(s1, g_hx.fork, 0);

    k_zero<<<NB, 256, 0, s1>>>();
    k_hist<<<EB, 256, 0, s1>>>(ei);
    k_scanA<<<NBLK, 256, 0, s1>>>();

    dim3 g1((NN + 127) / 128, HD1 / 128);
    k_gemm_fp16<128, 128, float><<<g1, 256, SM1>>>(x, W1, h1hp, NN, HD1);

    k_scanC<<<NBLK, 256, 0, s1>>>();
    k_scatter<<<EB, 256, 0, s1>>>(ei);
    cudaEventRecord(g_hx.join, s1);

    k_logits1<<<NWB, 256>>>(a1s, a1d);

    // join: gat1 needs both CSR and logits
    cudaStreamWaitEvent(0, g_hx.join, 0);
    dim3 gg1(NWB, 2);
    k_gat1<<<gg1, 256>>>(b1);

    dim3 g2((NN + 127) / 128, 1);
    k_gemm_fp16<64, 256, __half><<<g2, 256, SM2>>>(h1bp, W2, h2hp, NN, OUTC);
    k_logits2<<<NWB, 256>>>(a2s, a2d);
    k_gat2<<<NWB, 256>>>(b2, out);
}

// round 16
// speedup vs baseline: 1.3501x; 1.3501x over previous
#include <cuda_runtime.h>
#include <cuda_fp16.h>
#include <math.h>

#define NN    50000
#define EE    500000
#define ET    550000          // EE + NN self-loops
#define FIN   128
#define HD1   256             // HEADS*HID
#define HEADS 8
#define HID   32
#define OUTC  64
#define NBLK  196             // ceil(NN/256)
#define STA   8               // As row stride in words (16 halves, no pad; swizzled)

// ---------------- scratch (static device arrays; no cudaMalloc) -------------
__device__ __half g_h1h[NN * HD1];   // gemm1 output (fp16)
__device__ __half g_h1b[NN * HD1];   // layer-1 GAT output, post bias+ELU (fp16)
__device__ float  g_al1[NN * HEADS];
__device__ float  g_ar1[NN * HEADS];
__device__ __half g_h2h[NN * OUTC];  // gemm2 output (fp16)
__device__ float  g_al2[NN];
__device__ float  g_ar2[NN];

__device__ int g_deg  [NN];
__device__ int g_cur  [NN];
__device__ int g_start[NN];
__device__ int g_scan [NN];
__device__ int g_bsum [256];
__device__ int g_esrc [ET];

// ---------------- streams/events (host objects, created at static init) -----
struct HxStreams {
    cudaStream_t s1;
    cudaEvent_t fork, join;
    HxStreams() {
        cudaStreamCreateWithFlags(&s1, cudaStreamNonBlocking);
        cudaEventCreateWithFlags(&fork, cudaEventDisableTiming);
        cudaEventCreateWithFlags(&join, cudaEventDisableTiming);
    }
};
static HxStreams g_hx;

// ---------------- helpers ---------------------------------------------------
__device__ __forceinline__ float lrelu(float v) { return v > 0.f ? v : 0.2f * v; }

__device__ __forceinline__ int edge_dst(const int* __restrict__ ei, int e) {
    return (e < EE) ? ei[EE + e] : (e - EE);
}
__device__ __forceinline__ int edge_src(const int* __restrict__ ei, int e) {
    return (e < EE) ? ei[e] : (e - EE);
}

__device__ __forceinline__ unsigned packh2(float a, float b) {
    __half2 h = __floats2half2_rn(a, b);
    return *(unsigned*)&h;
}

__device__ __forceinline__ void mma_fp16(float c[4], const unsigned a[4], const unsigned b[2]) {
    asm volatile(
        "mma.sync.aligned.m16n8k16.row.col.f32.f16.f16.f32 "
        "{%0,%1,%2,%3}, {%4,%5,%6,%7}, {%8,%9}, {%0,%1,%2,%3};"
        : "+f"(c[0]), "+f"(c[1]), "+f"(c[2]), "+f"(c[3])
        : "r"(a[0]), "r"(a[1]), "r"(a[2]), "r"(a[3]), "r"(b[0]), "r"(b[1]));
}

// A-pair loader: produces pairs (k, k+1) and (k+8, k+9) as packed half2 words
__device__ __forceinline__ void load_a_pair(const float* p, unsigned& u0, unsigned& u1) {
    float2 f0 = *(const float2*)p;
    float2 f1 = *(const float2*)(p + 8);
    u0 = packh2(f0.x, f0.y);
    u1 = packh2(f1.x, f1.y);
}
__device__ __forceinline__ void load_a_pair(const __half* p, unsigned& u0, unsigned& u1) {
    u0 = *(const unsigned*)p;
    u1 = *(const unsigned*)(p + 8);
}

// ---------------- CSR build --------------------------------------------------
__global__ void k_zero() {
    int i = blockIdx.x * blockDim.x + threadIdx.x;
    if (i < NN) { g_deg[i] = 0; g_cur[i] = 0; }
}

__global__ void k_hist(const int* __restrict__ ei) {
    int e = blockIdx.x * blockDim.x + threadIdx.x;
    if (e >= ET) return;
    atomicAdd(&g_deg[edge_dst(ei, e)], 1);
}

__global__ void k_scanA() {
    __shared__ int s[256];
    int i = blockIdx.x * 256 + threadIdx.x;
    int v = (i < NN) ? g_deg[i] : 0;
    s[threadIdx.x] = v;
    __syncthreads();
    #pragma unroll
    for (int off = 1; off < 256; off <<= 1) {
        int t = (threadIdx.x >= off) ? s[threadIdx.x - off] : 0;
        __syncthreads();
        s[threadIdx.x] += t;
        __syncthreads();
    }
    if (i < NN) g_scan[i] = s[threadIdx.x];
    if (threadIdx.x == 255) g_bsum[blockIdx.x] = s[255];
}

__global__ void k_scanC() {
    __shared__ int red[256];
    int tid = threadIdx.x;
    red[tid] = (tid < (int)blockIdx.x) ? g_bsum[tid] : 0;
    __syncthreads();
    #pragma unroll
    for (int off = 128; off > 0; off >>= 1) {
        if (tid < off) red[tid] += red[tid + off];
        __syncthreads();
    }
    int base = red[0];
    int i = blockIdx.x * 256 + tid;
    if (i < NN) g_start[i] = g_scan[i] - g_deg[i] + base;
}

__global__ void k_scatter(const int* __restrict__ ei) {
    int e = blockIdx.x * blockDim.x + threadIdx.x;
    if (e >= ET) return;
    int d = edge_dst(ei, e);
    int pos = g_start[d] + atomicAdd(&g_cur[d], 1);
    g_esrc[pos] = edge_src(ei, e);
}

// ---------------- FP16 tensor-core GEMM, B resident in smem ------------------
// If LG (layer-1): fused attention-logit epilogue. Warp column wn covers one
// head (32 channels); per-thread partial dot + shfl over tig writes al/ar.
template<int BN, int KK, typename AT, bool LG>
__global__ __launch_bounds__(256, 2) void k_gemm_fp16(
    const AT* __restrict__ A, const float* __restrict__ B,
    __half* __restrict__ Ch, int nrows, int ncols,
    const float* __restrict__ a_src, const float* __restrict__ a_dst,
    float* __restrict__ al, float* __restrict__ ar)
{
    constexpr int WN  = BN / 32;
    constexpr int WM  = 8 / WN;
    constexpr int MT  = 128 / (WM * 16);
    constexpr int NT  = 4;
    constexpr int STB = KK / 2 + 8;     // B col stride (words); /2 ≡ 4 mod 16
    constexpr int NC  = KK / 16;

    extern __shared__ unsigned sm[];
    unsigned* Bs = sm;                  // [BN][STB]
    unsigned* As = sm + BN * STB;       // [128][STA]

    int tid = threadIdx.x;
    int lane = tid & 31, warp = tid >> 5;
    int g = lane >> 2, tig = lane & 3;
    int wm = warp % WM, wn = warp / WM;
    int rowBase = blockIdx.x * 128, colBase = blockIdx.y * BN;

    // ---- fill B slab once ----
    {
        int tig_f = tid >> 6;           // 0..3 : pair-slot
        int cc    = tid & 63;
        #pragma unroll
        for (int c16 = 0; c16 < NC; ++c16) {
            #pragma unroll
            for (int hb = 0; hb < BN / 64; ++hb) {
                int col = cc + hb * 64;
                const float* bp = B + (size_t)(c16 * 16 + 2 * tig_f) * ncols + colBase + col;
                float v0 = bp[0];
                float v1 = bp[(size_t)ncols];
                float v8 = bp[(size_t)8 * ncols];
                float v9 = bp[(size_t)9 * ncols];
                int slot = tig_f ^ (col & 3);
                *(uint2*)&Bs[col * STB + c16 * 8 + 2 * slot] =
                    make_uint2(packh2(v0, v1), packh2(v8, v9));
            }
        }
    }

    float c[MT][NT][4] = {};

    int tig_a = tid & 3, rr = tid >> 2;   // A fill: rows rr, rr+64; pair-slot tig_a
    unsigned au[2][2];

    // prefetch chunk 0
    #pragma unroll
    for (int r = 0; r < 2; ++r) {
        int grow = rowBase + rr + r * 64;
        if (grow < nrows)
            load_a_pair(A + (size_t)grow * KK + 2 * tig_a, au[r][0], au[r][1]);
        else { au[r][0] = 0u; au[r][1] = 0u; }
    }

    for (int kci = 0; kci < NC; ++kci) {
        #pragma unroll
        for (int r = 0; r < 2; ++r) {
            int row = rr + r * 64;
            *(uint2*)&As[row * STA + 2 * (tig_a ^ (row & 3))] =
                make_uint2(au[r][0], au[r][1]);
        }
        __syncthreads();

        if (kci + 1 < NC) {
            int kc = (kci + 1) * 16;
            #pragma unroll
            for (int r = 0; r < 2; ++r) {
                int grow = rowBase + rr + r * 64;
                if (grow < nrows)
                    load_a_pair(A + (size_t)grow * KK + kc + 2 * tig_a, au[r][0], au[r][1]);
                else { au[r][0] = 0u; au[r][1] = 0u; }
            }
        }

        unsigned a[MT][4], b[NT][2];
        int sw = 2 * (tig ^ (g & 3));
        #pragma unroll
        for (int mt = 0; mt < MT; ++mt) {
            int rlo = wm * (MT * 16) + mt * 16 + g;
            uint2 lo = *(const uint2*)&As[rlo * STA + sw];
            uint2 hi = *(const uint2*)&As[(rlo + 8) * STA + sw];
            a[mt][0] = lo.x; a[mt][2] = lo.y;
            a[mt][1] = hi.x; a[mt][3] = hi.y;
        }
        #pragma unroll
        for (int nt = 0; nt < NT; ++nt) {
            int cn = wn * 32 + nt * 8 + g;
            uint2 bb = *(const uint2*)&Bs[cn * STB + kci * 8 + sw];
            b[nt][0] = bb.x; b[nt][1] = bb.y;
        }
        #pragma unroll
        for (int mt = 0; mt < MT; ++mt)
            #pragma unroll
            for (int nt = 0; nt < NT; ++nt)
                mma_fp16(c[mt][nt], a[mt], b[nt]);
        __syncthreads();
    }

    // epilogue (fp16 out)
    #pragma unroll
    for (int mt = 0; mt < MT; ++mt) {
        #pragma unroll
        for (int nt = 0; nt < NT; ++nt) {
            int row0 = rowBase + wm * (MT * 16) + mt * 16 + g;
            int row1 = row0 + 8;
            int col  = colBase + wn * 32 + nt * 8 + tig * 2;
            if (row0 < nrows)
                *(__half2*)(Ch + (size_t)row0 * ncols + col) =
                    __floats2half2_rn(c[mt][nt][0], c[mt][nt][1]);
            if (row1 < nrows)
                *(__half2*)(Ch + (size_t)row1 * ncols + col) =
                    __floats2half2_rn(c[mt][nt][2], c[mt][nt][3]);
        }
    }

    if constexpr (LG) {
        // fused attention logits: head = by*WN + wn owns cols wn*32..+31
        int head = blockIdx.y * WN + wn;
        const float* as_ = a_src + head * HID;
        const float* ad_ = a_dst + head * HID;
        float av_[8], dv_[8];
        #pragma unroll
        for (int nt = 0; nt < NT; ++nt) {
            int cc = nt * 8 + tig * 2;
            av_[2 * nt] = as_[cc];     av_[2 * nt + 1] = as_[cc + 1];
            dv_[2 * nt] = ad_[cc];     dv_[2 * nt + 1] = ad_[cc + 1];
        }
        #pragma unroll
        for (int mt = 0; mt < MT; ++mt) {
            float s0 = 0.f, s1 = 0.f, d0 = 0.f, d1 = 0.f;
            #pragma unroll
            for (int nt = 0; nt < NT; ++nt) {
                s0 += c[mt][nt][0] * av_[2 * nt] + c[mt][nt][1] * av_[2 * nt + 1];
                d0 += c[mt][nt][0] * dv_[2 * nt] + c[mt][nt][1] * dv_[2 * nt + 1];
                s1 += c[mt][nt][2] * av_[2 * nt] + c[mt][nt][3] * av_[2 * nt + 1];
                d1 += c[mt][nt][2] * dv_[2 * nt] + c[mt][nt][3] * dv_[2 * nt + 1];
            }
            s0 += __shfl_xor_sync(0xffffffffu, s0, 1); s0 += __shfl_xor_sync(0xffffffffu, s0, 2);
            s1 += __shfl_xor_sync(0xffffffffu, s1, 1); s1 += __shfl_xor_sync(0xffffffffu, s1, 2);
            d0 += __shfl_xor_sync(0xffffffffu, d0, 1); d0 += __shfl_xor_sync(0xffffffffu, d0, 2);
            d1 += __shfl_xor_sync(0xffffffffu, d1, 1); d1 += __shfl_xor_sync(0xffffffffu, d1, 2);
            if (tig == 0) {
                int row0 = rowBase + wm * (MT * 16) + mt * 16 + g;
                int row1 = row0 + 8;
                if (row0 < nrows) { al[row0 * HEADS + head] = s0; ar[row0 * HEADS + head] = d0; }
                if (row1 < nrows) { al[row1 * HEADS + head] = s1; ar[row1 * HEADS + head] = d1; }
            }
        }
    }
}

// ---------------- fused layer-1 GAT (R12 form: 4-edge unroll, serial tail) ---
__global__ __launch_bounds__(256) void k_gat1(const float* __restrict__ b1) {
    int warp = threadIdx.x >> 5, lane = threadIdx.x & 31;
    int n = blockIdx.x * 8 + warp;
    if (n >= NN) return;
    int beg = g_start[n], deg = g_deg[n];
    int h = lane >> 2;
    float ard = g_ar1[n * HEADS + h];

    float sum = 0.f;
    float acc[8] = {};
    int i = 0;
    for (; i + 4 <= deg; i += 4) {
        int s0 = g_esrc[beg + i];
        int s1 = g_esrc[beg + i + 1];
        int s2 = g_esrc[beg + i + 2];
        int s3 = g_esrc[beg + i + 3];
        float p0 = __expf(lrelu(g_al1[s0 * HEADS + h] + ard));
        float p1 = __expf(lrelu(g_al1[s1 * HEADS + h] + ard));
        float p2 = __expf(lrelu(g_al1[s2 * HEADS + h] + ard));
        float p3 = __expf(lrelu(g_al1[s3 * HEADS + h] + ard));
        sum += (p0 + p1) + (p2 + p3);
        uint4 q0 = *((const uint4*)(g_h1h + (size_t)s0 * HD1) + lane);
        uint4 q1 = *((const uint4*)(g_h1h + (size_t)s1 * HD1) + lane);
        uint4 q2 = *((const uint4*)(g_h1h + (size_t)s2 * HD1) + lane);
        uint4 q3 = *((const uint4*)(g_h1h + (size_t)s3 * HD1) + lane);
        const __half2* h0 = (const __half2*)&q0;
        const __half2* h1 = (const __half2*)&q1;
        const __half2* h2 = (const __half2*)&q2;
        const __half2* h3 = (const __half2*)&q3;
        #pragma unroll
        for (int p = 0; p < 4; ++p) {
            float2 f0 = __half22float2(h0[p]);
            float2 f1 = __half22float2(h1[p]);
            float2 f2 = __half22float2(h2[p]);
            float2 f3 = __half22float2(h3[p]);
            acc[2 * p]     += (p0 * f0.x + p1 * f1.x) + (p2 * f2.x + p3 * f3.x);
            acc[2 * p + 1] += (p0 * f0.y + p1 * f1.y) + (p2 * f2.y + p3 * f3.y);
        }
    }
    for (; i < deg; ++i) {
        int s0 = g_esrc[beg + i];
        float p0 = __expf(lrelu(g_al1[s0 * HEADS + h] + ard));
        sum += p0;
        uint4 q0 = *((const uint4*)(g_h1h + (size_t)s0 * HD1) + lane);
        const __half2* h0 = (const __half2*)&q0;
        #pragma unroll
        for (int p = 0; p < 4; ++p) {
            float2 f0 = __half22float2(h0[p]);
            acc[2 * p]     += p0 * f0.x;
            acc[2 * p + 1] += p0 * f0.y;
        }
    }
    float r = 1.f / (sum + 1e-16f);
    int c = lane * 8;
    __half2 w[4];
    #pragma unroll
    for (int j = 0; j < 4; ++j) {
        float t0 = acc[2 * j] * r + b1[c + 2 * j];
        float t1 = acc[2 * j + 1] * r + b1[c + 2 * j + 1];
        t0 = t0 > 0.f ? t0 : expm1f(t0);
        t1 = t1 > 0.f ? t1 : expm1f(t1);
        w[j] = __floats2half2_rn(t0, t1);
    }
    *(uint4*)(g_h1b + (size_t)n * HD1 + c) = *(const uint4*)w;
}

// ---------------- layer-2 attention logits (fp16 h2) -------------------------
__global__ __launch_bounds__(256) void k_logits2(
    const float* __restrict__ a_src, const float* __restrict__ a_dst)
{
    int warp = threadIdx.x >> 5, lane = threadIdx.x & 31;
    int n = blockIdx.x * 8 + warp;
    if (n >= NN) return;
    float2 v = __half22float2(((const __half2*)(g_h2h + (size_t)n * OUTC))[lane]);
    int c = lane * 2;
    float sa = v.x * a_src[c] + v.y * a_src[c + 1];
    float sd = v.x * a_dst[c] + v.y * a_dst[c + 1];
    #pragma unroll
    for (int off = 16; off > 0; off >>= 1) {
        sa += __shfl_xor_sync(0xffffffffu, sa, off);
        sd += __shfl_xor_sync(0xffffffffu, sd, off);
    }
    if (lane == 0) { g_al2[n] = sa; g_ar2[n] = sd; }
}

// ---------------- fused layer-2 GAT + bias + log-softmax (4-edge unroll) ----
__global__ __launch_bounds__(256) void k_gat2(
    const float* __restrict__ b2, float* __restrict__ out)
{
    int warp = threadIdx.x >> 5, lane = threadIdx.x & 31;
    int n = blockIdx.x * 8 + warp;
    if (n >= NN) return;
    int beg = g_start[n], deg = g_deg[n];
    float ard = g_ar2[n];

    const __half* hbase = g_h2h + lane * 2;
    float sum = 0.f;
    float2 acc = make_float2(0.f, 0.f);
    int i = 0;
    for (; i + 4 <= deg; i += 4) {
        int s0 = g_esrc[beg + i];
        int s1 = g_esrc[beg + i + 1];
        int s2 = g_esrc[beg + i + 2];
        int s3 = g_esrc[beg + i + 3];
        float p0 = __expf(lrelu(g_al2[s0] + ard));
        float p1 = __expf(lrelu(g_al2[s1] + ard));
        float p2 = __expf(lrelu(g_al2[s2] + ard));
        float p3 = __expf(lrelu(g_al2[s3] + ard));
        sum += (p0 + p1) + (p2 + p3);
        float2 x0 = __half22float2(*(const __half2*)(hbase + (size_t)s0 * OUTC));
        float2 x1 = __half22float2(*(const __half2*)(hbase + (size_t)s1 * OUTC));
        float2 x2 = __half22float2(*(const __half2*)(hbase + (size_t)s2 * OUTC));
        float2 x3 = __half22float2(*(const __half2*)(hbase + (size_t)s3 * OUTC));
        acc.x += (p0 * x0.x + p1 * x1.x) + (p2 * x2.x + p3 * x3.x);
        acc.y += (p0 * x0.y + p1 * x1.y) + (p2 * x2.y + p3 * x3.y);
    }
    for (; i < deg; ++i) {
        int s0 = g_esrc[beg + i];
        float p0 = __expf(lrelu(g_al2[s0] + ard));
        sum += p0;
        float2 x0 = __half22float2(*(const __half2*)(hbase + (size_t)s0 * OUTC));
        acc.x += p0 * x0.x;
        acc.y += p0 * x0.y;
    }
    float r = 1.f / (sum + 1e-16f);
    int c = lane * 2;
    float v0 = acc.x * r + b2[c];
    float v1 = acc.y * r + b2[c + 1];

    float m = fmaxf(v0, v1);
    #pragma unroll
    for (int off = 16; off > 0; off >>= 1)
        m = fmaxf(m, __shfl_xor_sync(0xffffffffu, m, off));
    float ss = expf(v0 - m) + expf(v1 - m);
    #pragma unroll
    for (int off = 16; off > 0; off >>= 1)
        ss += __shfl_xor_sync(0xffffffffu, ss, off);
    float l = m + logf(ss);
    out[(size_t)n * OUTC + c]     = v0 - l;
    out[(size_t)n * OUTC + c + 1] = v1 - l;
}

// ---------------- launcher ---------------------------------------------------
extern "C" void kernel_launch(void* const* d_in, const int* in_sizes, int n_in,
                              void* d_out, int out_size)
{
    const float* x   = (const float*)d_in[0];
    const int*   ei  = (const int*)d_in[1];
    const float* W1  = (const float*)d_in[2];
    const float* a1s = (const float*)d_in[3];
    const float* a1d = (const float*)d_in[4];
    const float* b1  = (const float*)d_in[5];
    const float* W2  = (const float*)d_in[6];
    const float* a2s = (const float*)d_in[7];
    const float* a2d = (const float*)d_in[8];
    const float* b2  = (const float*)d_in[9];
    float* out = (float*)d_out;

    __half *h1hp, *h1bp, *h2hp;
    float *al1p, *ar1p;
    cudaGetSymbolAddress((void**)&h1hp, g_h1h);
    cudaGetSymbolAddress((void**)&h1bp, g_h1b);
    cudaGetSymbolAddress((void**)&h2hp, g_h2h);
    cudaGetSymbolAddress((void**)&al1p, g_al1);
    cudaGetSymbolAddress((void**)&ar1p, g_ar1);

    const int EB  = (ET + 255) / 256;
    const int NB  = (NN + 255) / 256;
    const int NWB = (NN + 7) / 8;

    const int SM1 = (128 * (128 / 2 + 8) + 128 * STA) * 4;   // 40960 B
    const int SM2 = (64 * (256 / 2 + 8) + 128 * STA) * 4;    // 38912 B
    cudaFuncSetAttribute(k_gemm_fp16<128, 128, float, true>,
                         cudaFuncAttributeMaxDynamicSharedMemorySize, SM1);
    cudaFuncSetAttribute(k_gemm_fp16<64, 256, __half, false>,
                         cudaFuncAttributeMaxDynamicSharedMemorySize, SM2);

    cudaStream_t s1 = g_hx.s1;

    // fork: CSR build on s1, concurrent with gemm1 (fused logits) on main
    cudaEventRecord(g_hx.fork, 0);
    cudaStreamWaitEvent(s1, g_hx.fork, 0);

    k_zero<<<NB, 256, 0, s1>>>();
    k_hist<<<EB, 256, 0, s1>>>(ei);
    k_scanA<<<NBLK, 256, 0, s1>>>();

    dim3 g1((NN + 127) / 128, HD1 / 128);
    k_gemm_fp16<128, 128, float, true><<<g1, 256, SM1>>>(
        x, W1, h1hp, NN, HD1, a1s, a1d, al1p, ar1p);

    k_scanC<<<NBLK, 256, 0, s1>>>();
    k_scatter<<<EB, 256, 0, s1>>>(ei);
    cudaEventRecord(g_hx.join, s1);

    // join: gat1 needs CSR + gemm1(logits)
    cudaStreamWaitEvent(0, g_hx.join, 0);
    k_gat1<<<NWB, 256>>>(b1);

    dim3 g2((NN + 127) / 128, 1);
    k_gemm_fp16<64, 256, __half, false><<<g2, 256, SM2>>>(
        h1bp, W2, h2hp, NN, OUTC, nullptr, nullptr, nullptr, nullptr);
    k_logits2<<<NWB, 256>>>(a2s, a2d);
    k_gat2<<<NWB, 256>>>(b2, out);
}